// round 1
// baseline (speedup 1.0000x reference)
#include <cuda_runtime.h>

#define EPSF 1e-10f

// Problem dims (fixed by the dataset)
//   B=512, P=100, Q=40, P2=40, D=64, Nu=Ni=100000, Nr=6

__device__ float g_hoI[512 * 40 * 64];  // h_oI  [B,Q,64]
__device__ float g_hiI[512 * 64];       // h_iI  [B,64]
__device__ float g_hiS[512 * 64];       // h_iS  [B,64]

// ---------------------------------------------------------------------------
// Warp-level 5-row x 64-col GEMM tile.
// sXT: transposed input, layout [K][8] (stride 8 floats, rows 0..4 used)
// sW : weights [K][64]
// Each lane owns output columns {2*lane, 2*lane+1}.
// ---------------------------------------------------------------------------
template <int K>
__device__ __forceinline__ void wgemm(const float* __restrict__ sXT,
                                      const float* __restrict__ sW,
                                      int lane, float acc[5][2]) {
#pragma unroll 8
  for (int k = 0; k < K; k++) {
    float2 w = *reinterpret_cast<const float2*>(sW + k * 64 + 2 * lane);
    float4 x4 = *reinterpret_cast<const float4*>(sXT + k * 8);
    float x5 = sXT[k * 8 + 4];
    acc[0][0] = fmaf(x4.x, w.x, acc[0][0]); acc[0][1] = fmaf(x4.x, w.y, acc[0][1]);
    acc[1][0] = fmaf(x4.y, w.x, acc[1][0]); acc[1][1] = fmaf(x4.y, w.y, acc[1][1]);
    acc[2][0] = fmaf(x4.z, w.x, acc[2][0]); acc[2][1] = fmaf(x4.z, w.y, acc[2][1]);
    acc[3][0] = fmaf(x4.w, w.x, acc[3][0]); acc[3][1] = fmaf(x4.w, w.y, acc[3][1]);
    acc[4][0] = fmaf(x5,  w.x, acc[4][0]);  acc[4][1] = fmaf(x5,  w.y, acc[4][1]);
  }
}

__device__ __forceinline__ void wtrans(float* sT, int lane, const float acc[5][2]) {
#pragma unroll
  for (int j = 0; j < 5; j++) {
    sT[(2 * lane) * 8 + j]     = acc[j][0];
    sT[(2 * lane + 1) * 8 + j] = acc[j][1];
  }
}

// gv MLP (128->64 relu ->64) + atti attention MLP (->score) for one 5-row tile.
// x already staged (transposed) in myXT. Writes x_ia rows into sXia and
// exp(score)*mask into sAlpha.
__device__ __forceinline__ void tile_gv_atti(
    float* myXT, int lane,
    const float* sW1, const float* sb1, const float* sW2, const float* sb2,
    const float* sA1, const float* sb1a, const float* spC, const float* sw2a,
    float cb2a, const float msk[5], int rowbase, int nrows_store,
    float* sXia, float* sAlpha) {
  float acc[5][2];
#pragma unroll
  for (int j = 0; j < 5; j++) { acc[j][0] = sb1[2 * lane]; acc[j][1] = sb1[2 * lane + 1]; }
  wgemm<128>(myXT, sW1, lane, acc);
#pragma unroll
  for (int j = 0; j < 5; j++) { acc[j][0] = fmaxf(acc[j][0], 0.f); acc[j][1] = fmaxf(acc[j][1], 0.f); }
  __syncwarp();
  wtrans(myXT, lane, acc);
  __syncwarp();
#pragma unroll
  for (int j = 0; j < 5; j++) { acc[j][0] = sb2[2 * lane]; acc[j][1] = sb2[2 * lane + 1]; }
  wgemm<64>(myXT, sW2, lane, acc);   // acc = x_ia (no relu)

#pragma unroll
  for (int j = 0; j < 5; j++) {
    int row = rowbase + j;
    if (row < nrows_store) {
      sXia[row * 64 + 2 * lane]     = acc[j][0];
      sXia[row * 64 + 2 * lane + 1] = acc[j][1];
    }
  }
  __syncwarp();
  wtrans(myXT, lane, acc);
  __syncwarp();
  float acc2[5][2];
#pragma unroll
  for (int j = 0; j < 5; j++) {
    acc2[j][0] = fmaf(msk[j], spC[2 * lane],     sb1a[2 * lane]);
    acc2[j][1] = fmaf(msk[j], spC[2 * lane + 1], sb1a[2 * lane + 1]);
  }
  wgemm<64>(myXT, sA1, lane, acc2);
  float w0 = sw2a[2 * lane], w1 = sw2a[2 * lane + 1];
#pragma unroll
  for (int j = 0; j < 5; j++) {
    float p = fmaf(fmaxf(acc2[j][0], 0.f), w0, fmaxf(acc2[j][1], 0.f) * w1);
#pragma unroll
    for (int o = 16; o; o >>= 1) p += __shfl_xor_sync(0xffffffffu, p, o);
    if (lane == 0) sAlpha[rowbase + j] = expf(p + cb2a) * msk[j];
  }
}

// ---------------------------------------------------------------------------
// K1: item branch -> g_hiI[b][64]. One CTA per batch element (100 item rows).
// smem floats: W1 8192 | W2 4096 | A1 4096 | Agg 4096 | w2a/pC/b1/b2/b1a/bAgg/P/Z 64*8
//            | Alpha 128 | Red 8 | XT 8*1024 | Xia 100*64
// ---------------------------------------------------------------------------
#define SMEM_K1 (35720 * 4)
__global__ __launch_bounds__(256) void k1_item(
    const int* __restrict__ uids, const int* __restrict__ u_item,
    const float* __restrict__ user_table, const float* __restrict__ item_table,
    const float* __restrict__ rate_table,
    const float* __restrict__ gv_W1, const float* __restrict__ gv_b1,
    const float* __restrict__ gv_W2, const float* __restrict__ gv_b2,
    const float* __restrict__ atti_W1, const float* __restrict__ atti_b1,
    const float* __restrict__ atti_W2, const float* __restrict__ atti_b2,
    const float* __restrict__ agg_W, const float* __restrict__ agg_b) {
  extern __shared__ float sm[];
  float* sW1 = sm;            float* sW2 = sm + 8192;
  float* sA1 = sm + 12288;    float* sAgg = sm + 16384;
  float* sw2a = sm + 20480;   float* spC = sm + 20544;
  float* sb1 = sm + 20608;    float* sb2 = sm + 20672;
  float* sb1a = sm + 20736;   float* sbAgg = sm + 20800;
  float* sP = sm + 20864;     float* sZ = sm + 20928;
  float* sAlpha = sm + 20992; float* sRed = sm + 21120;
  float* sXT = sm + 21128;    float* sXia = sm + 29320;

  int b = blockIdx.x, tid = threadIdx.x, lane = tid & 31, w = tid >> 5;
  for (int i = tid; i < 8192; i += 256) sW1[i] = gv_W1[i];
  for (int i = tid; i < 4096; i += 256) { sW2[i] = gv_W2[i]; sA1[i] = atti_W1[i]; sAgg[i] = agg_W[i]; }
  if (tid < 64) {
    sw2a[tid] = atti_W2[tid]; sb1[tid] = gv_b1[tid]; sb2[tid] = gv_b2[tid];
    sb1a[tid] = atti_b1[tid]; sbAgg[tid] = agg_b[tid];
    sP[tid] = user_table[(long)uids[b] * 64 + tid];
  }
  __syncthreads();
  if (tid < 64) {
    float s = 0.f; const float* A1b = atti_W1 + 4096;
#pragma unroll 8
    for (int k = 0; k < 64; k++) s = fmaf(sP[k], A1b[k * 64 + tid], s);
    spC[tid] = s;
  }
  __syncthreads();
  float cb2a = atti_b2[0];
  float* myXT = sXT + w * 1024;
  for (int pass = 0; pass < 3; pass++) {
    int rowbase = pass * 40 + w * 5;
    float msk[5];
#pragma unroll
    for (int j = 0; j < 5; j++) {
      int row = rowbase + j;
      float a0 = 0, a1 = 0, r0 = 0, r1 = 0, m = 0;
      if (row < 100) {
        int i0 = u_item[(b * 100 + row) * 2];
        int i1 = u_item[(b * 100 + row) * 2 + 1];
        m = (i0 > 0) ? 1.f : 0.f;
        const float* ip = item_table + (long)i0 * 64;
        const float* rp = rate_table + (long)i1 * 64;
        a0 = ip[lane]; a1 = ip[lane + 32]; r0 = rp[lane]; r1 = rp[lane + 32];
      }
      msk[j] = m;
      myXT[lane * 8 + j] = a0; myXT[(lane + 32) * 8 + j] = a1;
      myXT[(lane + 64) * 8 + j] = r0; myXT[(lane + 96) * 8 + j] = r1;
    }
    __syncwarp();
    tile_gv_atti(myXT, lane, sW1, sb1, sW2, sb2, sA1, sb1a, spC, sw2a, cb2a,
                 msk, rowbase, 100, sXia, sAlpha);
  }
  __syncthreads();
  if (tid < 32) {
    float s = 0.f;
    for (int r = lane; r < 120; r += 32) s += sAlpha[r];
#pragma unroll
    for (int o = 16; o; o >>= 1) s += __shfl_xor_sync(0xffffffffu, s, o);
    if (lane == 0) sRed[0] = s;
  }
  __syncthreads();
  float dinv = 1.f / (sRed[0] + EPSF);
  if (tid < 64) {
    float s = 0.f;
    for (int r = 0; r < 100; r++) s = fmaf(sAlpha[r], sXia[r * 64 + tid], s);
    sZ[tid] = s * dinv;
  }
  __syncthreads();
  if (tid < 64) {
    float s = sbAgg[tid];
    for (int k = 0; k < 64; k++) s = fmaf(sZ[k], sAgg[k * 64 + tid], s);
    g_hiI[b * 64 + tid] = fmaxf(s, 0.f);
  }
}

// ---------------------------------------------------------------------------
// K2a: social h_oI for all (b,q). Grid 512*5, each CTA does 8 q's of 40 rows.
// ---------------------------------------------------------------------------
#define SMEM_K2A (31880 * 4)
__global__ __launch_bounds__(256) void k2a_social(
    const int* __restrict__ u_user, const int* __restrict__ u_user_item,
    const float* __restrict__ user_table, const float* __restrict__ item_table,
    const float* __restrict__ rate_table,
    const float* __restrict__ gv_W1, const float* __restrict__ gv_b1,
    const float* __restrict__ gv_W2, const float* __restrict__ gv_b2,
    const float* __restrict__ atti_W1, const float* __restrict__ atti_b1,
    const float* __restrict__ atti_W2, const float* __restrict__ atti_b2,
    const float* __restrict__ agg_W, const float* __restrict__ agg_b) {
  extern __shared__ float sm[];
  float* sW1 = sm;            float* sW2 = sm + 8192;
  float* sA1 = sm + 12288;    float* sAgg = sm + 16384;
  float* sw2a = sm + 20480;   float* spC = sm + 20544;
  float* sb1 = sm + 20608;    float* sb2 = sm + 20672;
  float* sb1a = sm + 20736;   float* sbAgg = sm + 20800;
  float* sP = sm + 20864;     float* sZ = sm + 20928;
  float* sAlpha = sm + 20992; float* sRed = sm + 21120;
  float* sXT = sm + 21128;    float* sXia = sm + 29320;  // 40*64

  int bx = blockIdx.x, tid = threadIdx.x, lane = tid & 31, w = tid >> 5;
  int b = bx / 5, qbase = (bx % 5) * 8;
  for (int i = tid; i < 8192; i += 256) sW1[i] = gv_W1[i];
  for (int i = tid; i < 4096; i += 256) { sW2[i] = gv_W2[i]; sA1[i] = atti_W1[i]; sAgg[i] = agg_W[i]; }
  if (tid < 64) {
    sw2a[tid] = atti_W2[tid]; sb1[tid] = gv_b1[tid]; sb2[tid] = gv_b2[tid];
    sb1a[tid] = atti_b1[tid]; sbAgg[tid] = agg_b[tid];
  }
  __syncthreads();
  float cb2a = atti_b2[0];
  float* myXT = sXT + w * 1024;

  for (int qi = 0; qi < 8; qi++) {
    int q = qbase + qi;
    __syncthreads();
    if (tid < 64) sP[tid] = user_table[(long)u_user[b * 40 + q] * 64 + tid];
    __syncthreads();
    if (tid < 64) {
      float s = 0.f; const float* A1b = atti_W1 + 4096;
#pragma unroll 8
      for (int k = 0; k < 64; k++) s = fmaf(sP[k], A1b[k * 64 + tid], s);
      spC[tid] = s;
    }
    __syncthreads();
    int rowbase = w * 5;
    float msk[5];
#pragma unroll
    for (int j = 0; j < 5; j++) {
      int row = rowbase + j;
      int base = ((b * 40 + q) * 40 + row) * 2;
      int i0 = u_user_item[base], i1 = u_user_item[base + 1];
      msk[j] = (i0 > 0) ? 1.f : 0.f;
      const float* ip = item_table + (long)i0 * 64;
      const float* rp = rate_table + (long)i1 * 64;
      myXT[lane * 8 + j] = ip[lane]; myXT[(lane + 32) * 8 + j] = ip[lane + 32];
      myXT[(lane + 64) * 8 + j] = rp[lane]; myXT[(lane + 96) * 8 + j] = rp[lane + 32];
    }
    __syncwarp();
    tile_gv_atti(myXT, lane, sW1, sb1, sW2, sb2, sA1, sb1a, spC, sw2a, cb2a,
                 msk, rowbase, 40, sXia, sAlpha);
    __syncthreads();
    if (tid < 32) {
      float s = 0.f;
      for (int r = lane; r < 40; r += 32) s += sAlpha[r];
#pragma unroll
      for (int o = 16; o; o >>= 1) s += __shfl_xor_sync(0xffffffffu, s, o);
      if (lane == 0) sRed[0] = s;
    }
    __syncthreads();
    float dinv = 1.f / (sRed[0] + EPSF);
    if (tid < 64) {
      float s = 0.f;
      for (int r = 0; r < 40; r++) s = fmaf(sAlpha[r], sXia[r * 64 + tid], s);
      sZ[tid] = s * dinv;
    }
    __syncthreads();
    if (tid < 64) {
      float s = sbAgg[tid];
      for (int k = 0; k < 64; k++) s = fmaf(sZ[k], sAgg[k * 64 + tid], s);
      g_hoI[(b * 40 + q) * 64 + tid] = fmaxf(s, 0.f);
    }
  }
}

// ---------------------------------------------------------------------------
// K2b: beta attention over q + h_iS. One CTA per b (40 rows, exactly 8 warps x 5).
// ---------------------------------------------------------------------------
#define SMEM_K2B (20784 * 4)
__global__ __launch_bounds__(256) void k2b_user(
    const int* __restrict__ u_user, const float* __restrict__ user_table,
    const float* __restrict__ attu_W1, const float* __restrict__ attu_b1,
    const float* __restrict__ attu_W2, const float* __restrict__ attu_b2,
    const float* __restrict__ aggn_W, const float* __restrict__ aggn_b) {
  extern __shared__ float sm[];
  float* sU1 = sm;             float* sAggn = sm + 8192;
  float* sw2u = sm + 12288;    float* sb1u = sm + 12352;
  float* sbAggn = sm + 12416;  float* sZ = sm + 12480;
  float* sBeta = sm + 12544;   float* sRed = sm + 12584;
  float* sXT = sm + 12592;

  int b = blockIdx.x, tid = threadIdx.x, lane = tid & 31, w = tid >> 5;
  for (int i = tid; i < 8192; i += 256) sU1[i] = attu_W1[i];
  for (int i = tid; i < 4096; i += 256) sAggn[i] = aggn_W[i];
  if (tid < 64) { sw2u[tid] = attu_W2[tid]; sb1u[tid] = attu_b1[tid]; sbAggn[tid] = aggn_b[tid]; }
  __syncthreads();
  float cb2u = attu_b2[0];
  float* myXT = sXT + w * 1024;
  int rowbase = w * 5;
  float msk[5];
#pragma unroll
  for (int j = 0; j < 5; j++) {
    int row = rowbase + j;
    int uq = u_user[b * 40 + row];
    msk[j] = (uq > 0) ? 1.f : 0.f;
    const float* hp = g_hoI + (long)(b * 40 + row) * 64;
    const float* up = user_table + (long)uq * 64;
    myXT[lane * 8 + j] = hp[lane]; myXT[(lane + 32) * 8 + j] = hp[lane + 32];
    myXT[(lane + 64) * 8 + j] = up[lane]; myXT[(lane + 96) * 8 + j] = up[lane + 32];
  }
  __syncwarp();
  float acc[5][2];
#pragma unroll
  for (int j = 0; j < 5; j++) { acc[j][0] = sb1u[2 * lane]; acc[j][1] = sb1u[2 * lane + 1]; }
  wgemm<128>(myXT, sU1, lane, acc);
  float w0 = sw2u[2 * lane], w1 = sw2u[2 * lane + 1];
#pragma unroll
  for (int j = 0; j < 5; j++) {
    float p = fmaf(fmaxf(acc[j][0], 0.f), w0, fmaxf(acc[j][1], 0.f) * w1);
#pragma unroll
    for (int o = 16; o; o >>= 1) p += __shfl_xor_sync(0xffffffffu, p, o);
    if (lane == 0) sBeta[rowbase + j] = expf(p + cb2u) * msk[j];
  }
  __syncthreads();
  if (tid < 32) {
    float s = 0.f;
    for (int r = lane; r < 40; r += 32) s += sBeta[r];
#pragma unroll
    for (int o = 16; o; o >>= 1) s += __shfl_xor_sync(0xffffffffu, s, o);
    if (lane == 0) sRed[0] = s;
  }
  __syncthreads();
  float dinv = 1.f / (sRed[0] + EPSF);
  if (tid < 64) {
    float s = 0.f;
    for (int r = 0; r < 40; r++) s = fmaf(sBeta[r], g_hoI[(long)(b * 40 + r) * 64 + tid], s);
    sZ[tid] = s * dinv;
  }
  __syncthreads();
  if (tid < 64) {
    float s = sbAggn[tid];
    for (int k = 0; k < 64; k++) s = fmaf(sZ[k], sAggn[k * 64 + tid], s);
    g_hiS[b * 64 + tid] = fmaxf(s, 0.f);
  }
}

// ---------------------------------------------------------------------------
// K3: final 3-layer combine MLP over B=512 rows. Grid 13 CTAs x 40 rows.
// ---------------------------------------------------------------------------
#define SMEM_K3 (24768 * 4)
__global__ __launch_bounds__(256) void k3_final(
    const float* __restrict__ cm_W1, const float* __restrict__ cm_b1,
    const float* __restrict__ cm_W2, const float* __restrict__ cm_b2,
    const float* __restrict__ cm_W3, const float* __restrict__ cm_b3,
    float* __restrict__ out) {
  extern __shared__ float sm[];
  float* sC1 = sm;          float* sC2 = sm + 8192;   float* sC3 = sm + 12288;
  float* sb1 = sm + 16384;  float* sb2 = sm + 16448;  float* sb3 = sm + 16512;
  float* sXT = sm + 16576;

  int tid = threadIdx.x, lane = tid & 31, w = tid >> 5;
  for (int i = tid; i < 8192; i += 256) sC1[i] = cm_W1[i];
  for (int i = tid; i < 4096; i += 256) { sC2[i] = cm_W2[i]; sC3[i] = cm_W3[i]; }
  if (tid < 64) { sb1[tid] = cm_b1[tid]; sb2[tid] = cm_b2[tid]; sb3[tid] = cm_b3[tid]; }
  __syncthreads();
  float* myXT = sXT + w * 1024;
  int rowbase = blockIdx.x * 40 + w * 5;
#pragma unroll
  for (int j = 0; j < 5; j++) {
    int row = rowbase + j;
    float x0 = 0, x1 = 0, x2 = 0, x3 = 0;
    if (row < 512) {
      x0 = g_hiI[row * 64 + lane]; x1 = g_hiI[row * 64 + 32 + lane];
      x2 = g_hiS[row * 64 + lane]; x3 = g_hiS[row * 64 + 32 + lane];
    }
    myXT[lane * 8 + j] = x0; myXT[(lane + 32) * 8 + j] = x1;
    myXT[(lane + 64) * 8 + j] = x2; myXT[(lane + 96) * 8 + j] = x3;
  }
  __syncwarp();
  float acc[5][2];
#pragma unroll
  for (int j = 0; j < 5; j++) { acc[j][0] = sb1[2 * lane]; acc[j][1] = sb1[2 * lane + 1]; }
  wgemm<128>(myXT, sC1, lane, acc);
#pragma unroll
  for (int j = 0; j < 5; j++) { acc[j][0] = fmaxf(acc[j][0], 0.f); acc[j][1] = fmaxf(acc[j][1], 0.f); }
  __syncwarp(); wtrans(myXT, lane, acc); __syncwarp();
#pragma unroll
  for (int j = 0; j < 5; j++) { acc[j][0] = sb2[2 * lane]; acc[j][1] = sb2[2 * lane + 1]; }
  wgemm<64>(myXT, sC2, lane, acc);
#pragma unroll
  for (int j = 0; j < 5; j++) { acc[j][0] = fmaxf(acc[j][0], 0.f); acc[j][1] = fmaxf(acc[j][1], 0.f); }
  __syncwarp(); wtrans(myXT, lane, acc); __syncwarp();
#pragma unroll
  for (int j = 0; j < 5; j++) { acc[j][0] = sb3[2 * lane]; acc[j][1] = sb3[2 * lane + 1]; }
  wgemm<64>(myXT, sC3, lane, acc);
#pragma unroll
  for (int j = 0; j < 5; j++) {
    int row = rowbase + j;
    if (row < 512) {
      out[row * 64 + 2 * lane]     = fmaxf(acc[j][0], 0.f);
      out[row * 64 + 2 * lane + 1] = fmaxf(acc[j][1], 0.f);
    }
  }
}

// ---------------------------------------------------------------------------
extern "C" void kernel_launch(void* const* d_in, const int* in_sizes, int n_in,
                              void* d_out, int out_size) {
  const int* uids        = (const int*)d_in[0];
  const int* u_item      = (const int*)d_in[1];
  const int* u_user      = (const int*)d_in[2];
  const int* u_user_item = (const int*)d_in[3];
  const float* user_table = (const float*)d_in[4];
  const float* item_table = (const float*)d_in[5];
  const float* rate_table = (const float*)d_in[6];
  const float* gv_W1 = (const float*)d_in[7];   const float* gv_b1 = (const float*)d_in[8];
  const float* gv_W2 = (const float*)d_in[9];   const float* gv_b2 = (const float*)d_in[10];
  const float* atti_W1 = (const float*)d_in[11]; const float* atti_b1 = (const float*)d_in[12];
  const float* atti_W2 = (const float*)d_in[13]; const float* atti_b2 = (const float*)d_in[14];
  const float* agg_W = (const float*)d_in[15];   const float* agg_b = (const float*)d_in[16];
  const float* attu_W1 = (const float*)d_in[17]; const float* attu_b1 = (const float*)d_in[18];
  const float* attu_W2 = (const float*)d_in[19]; const float* attu_b2 = (const float*)d_in[20];
  const float* aggn_W = (const float*)d_in[21];  const float* aggn_b = (const float*)d_in[22];
  const float* cm_W1 = (const float*)d_in[23];   const float* cm_b1 = (const float*)d_in[24];
  const float* cm_W2 = (const float*)d_in[25];   const float* cm_b2 = (const float*)d_in[26];
  const float* cm_W3 = (const float*)d_in[27];   const float* cm_b3 = (const float*)d_in[28];
  float* out = (float*)d_out;

  cudaFuncSetAttribute(k1_item,    cudaFuncAttributeMaxDynamicSharedMemorySize, SMEM_K1);
  cudaFuncSetAttribute(k2a_social, cudaFuncAttributeMaxDynamicSharedMemorySize, SMEM_K2A);
  cudaFuncSetAttribute(k2b_user,   cudaFuncAttributeMaxDynamicSharedMemorySize, SMEM_K2B);
  cudaFuncSetAttribute(k3_final,   cudaFuncAttributeMaxDynamicSharedMemorySize, SMEM_K3);

  k2a_social<<<512 * 5, 256, SMEM_K2A>>>(u_user, u_user_item, user_table, item_table,
                                         rate_table, gv_W1, gv_b1, gv_W2, gv_b2,
                                         atti_W1, atti_b1, atti_W2, atti_b2, agg_W, agg_b);
  k1_item<<<512, 256, SMEM_K1>>>(uids, u_item, user_table, item_table, rate_table,
                                 gv_W1, gv_b1, gv_W2, gv_b2,
                                 atti_W1, atti_b1, atti_W2, atti_b2, agg_W, agg_b);
  k2b_user<<<512, 256, SMEM_K2B>>>(u_user, user_table, attu_W1, attu_b1, attu_W2,
                                   attu_b2, aggn_W, aggn_b);
  k3_final<<<13, 256, SMEM_K3>>>(cm_W1, cm_b1, cm_W2, cm_b2, cm_W3, cm_b3, out);
}

// round 3
// speedup vs baseline: 2.2840x; 2.2840x over previous
#include <cuda_runtime.h>

#define EPSF 1e-10f
#define NI 100000
#define NU 100000
#define NR 6
#define BB 512
#define PP 100
#define QQ 40
#define P2 40

// ---------------- persistent scratch (static device memory) -----------------
__device__ float g_iP[NI * 64];          // item_table @ W1_top
__device__ float g_uPA1[NU * 64];        // user_table @ A1_bot
__device__ float g_rP[NR * 64];          // rate_table @ W1_bot + gv_b1
__device__ float g_T1[(long)NR * NI * 64]; // x_ia per (rate,item)
__device__ float g_T2[(long)NR * NI * 64]; // x_ia@A1_top + b1a per (rate,item)
__device__ float g_hoI[BB * QQ * 64];
__device__ float g_hiI[BB * 64];
__device__ float g_hiS[BB * 64];

// ---------------------------------------------------------------------------
// Warp-level 5-row x 64-col GEMM tile.
// sXT: transposed input [K][8] (stride 8 floats, rows 0..4 used)
// sW : weights [K][64]; lane owns cols {2*lane, 2*lane+1}.
// ---------------------------------------------------------------------------
template <int K>
__device__ __forceinline__ void wgemm(const float* __restrict__ sXT,
                                      const float* __restrict__ sW,
                                      int lane, float acc[5][2]) {
#pragma unroll 8
  for (int k = 0; k < K; k++) {
    float2 w = *reinterpret_cast<const float2*>(sW + k * 64 + 2 * lane);
    float4 x4 = *reinterpret_cast<const float4*>(sXT + k * 8);
    float x5 = sXT[k * 8 + 4];
    acc[0][0] = fmaf(x4.x, w.x, acc[0][0]); acc[0][1] = fmaf(x4.x, w.y, acc[0][1]);
    acc[1][0] = fmaf(x4.y, w.x, acc[1][0]); acc[1][1] = fmaf(x4.y, w.y, acc[1][1]);
    acc[2][0] = fmaf(x4.z, w.x, acc[2][0]); acc[2][1] = fmaf(x4.z, w.y, acc[2][1]);
    acc[3][0] = fmaf(x4.w, w.x, acc[3][0]); acc[3][1] = fmaf(x4.w, w.y, acc[3][1]);
    acc[4][0] = fmaf(x5,  w.x, acc[4][0]);  acc[4][1] = fmaf(x5,  w.y, acc[4][1]);
  }
}

__device__ __forceinline__ void wtrans(float* sT, int lane, const float acc[5][2]) {
#pragma unroll
  for (int j = 0; j < 5; j++) {
    sT[(2 * lane) * 8 + j]     = acc[j][0];
    sT[(2 * lane + 1) * 8 + j] = acc[j][1];
  }
}

// ---------------------------------------------------------------------------
// K0_rp: rate_table @ W1_bot + b1  -> g_rP [6][64].  1 block, 384 threads.
// ---------------------------------------------------------------------------
__global__ void k0_rp(const float* __restrict__ rate_table,
                      const float* __restrict__ gv_W1,
                      const float* __restrict__ gv_b1) {
  int t = threadIdx.x;
  if (t >= NR * 64) return;
  int r = t >> 6, c = t & 63;
  float s = gv_b1[c];
  const float* W1b = gv_W1 + 64 * 64;  // bottom half rows
#pragma unroll 8
  for (int k = 0; k < 64; k++) s = fmaf(rate_table[r * 64 + k], W1b[k * 64 + c], s);
  g_rP[t] = s;
}

// ---------------------------------------------------------------------------
// K0_proj: rows [0,100000): g_iP = item_table @ W1_top (no bias)
//          rows [100000,200000): g_uPA1 = user_table @ A1_bot (no bias)
// grid 625, 256 thr, 8 warps x 5 rows x 8 iters = 320 rows/CTA.
// ---------------------------------------------------------------------------
#define SMEM_K0P ((4096 + 4096 + 4096) * 4)
__global__ __launch_bounds__(256) void k0_proj(
    const float* __restrict__ item_table, const float* __restrict__ user_table,
    const float* __restrict__ gv_W1, const float* __restrict__ atti_W1) {
  extern __shared__ float sm[];
  float* sWa = sm;            // W1_top
  float* sWb = sm + 4096;     // A1_bot
  float* sXT = sm + 8192;     // 8 warps x 512

  int tid = threadIdx.x, lane = tid & 31, w = tid >> 5;
  for (int i = tid; i < 4096; i += 256) { sWa[i] = gv_W1[i]; sWb[i] = atti_W1[4096 + i]; }
  __syncthreads();
  float* myXT = sXT + w * 512;

  for (int it = 0; it < 8; it++) {
    int rid0 = blockIdx.x * 320 + it * 40 + w * 5;
    bool half2 = (rid0 >= NI);
    const float* src = half2 ? user_table : item_table;
    const float* W = half2 ? sWb : sWa;
    float* dst = half2 ? g_uPA1 : g_iP;
    int base = half2 ? (rid0 - NI) : rid0;
#pragma unroll
    for (int j = 0; j < 5; j++) {
      const float* sp = src + (long)(base + j) * 64;
      myXT[lane * 8 + j] = sp[lane];
      myXT[(lane + 32) * 8 + j] = sp[lane + 32];
    }
    __syncwarp();
    float acc[5][2];
#pragma unroll
    for (int j = 0; j < 5; j++) { acc[j][0] = 0.f; acc[j][1] = 0.f; }
    wgemm<64>(myXT, W, lane, acc);
#pragma unroll
    for (int j = 0; j < 5; j++) {
      *reinterpret_cast<float2*>(dst + (long)(base + j) * 64 + 2 * lane) =
          make_float2(acc[j][0], acc[j][1]);
    }
    __syncwarp();
  }
}

// ---------------------------------------------------------------------------
// K0_combo: for all 600000 (rate,item) combos:
//   h1 = relu(iP[i] + rP[r])          (b1 folded into rP)
//   T1 = h1 @ W2 + b2                 (= x_ia)
//   T2 = T1 @ A1_top + b1a
// grid 1875, 256 thr, 320 rows/CTA.
// ---------------------------------------------------------------------------
#define SMEM_K0C ((4096 + 4096 + 4096 + 384 + 64 + 64) * 4)
__global__ __launch_bounds__(256) void k0_combo(
    const float* __restrict__ gv_W2, const float* __restrict__ gv_b2,
    const float* __restrict__ atti_W1, const float* __restrict__ atti_b1) {
  extern __shared__ float sm[];
  float* sW2 = sm;            // 4096
  float* sA1t = sm + 4096;    // 4096 (A1_top)
  float* sXT = sm + 8192;     // 4096
  float* srP = sm + 12288;    // 384
  float* sb2 = sm + 12672;    // 64
  float* sb1a = sm + 12736;   // 64

  int tid = threadIdx.x, lane = tid & 31, w = tid >> 5;
  for (int i = tid; i < 4096; i += 256) { sW2[i] = gv_W2[i]; sA1t[i] = atti_W1[i]; }
  for (int i = tid; i < 384; i += 256) srP[i] = g_rP[i];   // FIX: was `if (tid<384)` with 256 threads
  if (tid < 64) { sb2[tid] = gv_b2[tid]; sb1a[tid] = atti_b1[tid]; }
  __syncthreads();
  float* myXT = sXT + w * 512;

  for (int it = 0; it < 8; it++) {
    int rid0 = blockIdx.x * 320 + it * 40 + w * 5;
    int i0 = rid0 % NI;                  // item index of first row (rows consecutive)
    int r = rid0 / NI;                   // rate index (constant across 5-row tile)
    const float* rp = srP + r * 64;
#pragma unroll
    for (int j = 0; j < 5; j++) {
      const float* ip = g_iP + (long)(i0 + j) * 64;
      myXT[lane * 8 + j] = fmaxf(ip[lane] + rp[lane], 0.f);
      myXT[(lane + 32) * 8 + j] = fmaxf(ip[lane + 32] + rp[lane + 32], 0.f);
    }
    __syncwarp();
    float acc[5][2];
#pragma unroll
    for (int j = 0; j < 5; j++) { acc[j][0] = sb2[2 * lane]; acc[j][1] = sb2[2 * lane + 1]; }
    wgemm<64>(myXT, sW2, lane, acc);
#pragma unroll
    for (int j = 0; j < 5; j++) {
      *reinterpret_cast<float2*>(g_T1 + (long)(rid0 + j) * 64 + 2 * lane) =
          make_float2(acc[j][0], acc[j][1]);
    }
    __syncwarp();
    wtrans(myXT, lane, acc);
    __syncwarp();
    float acc2[5][2];
#pragma unroll
    for (int j = 0; j < 5; j++) { acc2[j][0] = sb1a[2 * lane]; acc2[j][1] = sb1a[2 * lane + 1]; }
    wgemm<64>(myXT, sA1t, lane, acc2);
#pragma unroll
    for (int j = 0; j < 5; j++) {
      *reinterpret_cast<float2*>(g_T2 + (long)(rid0 + j) * 64 + 2 * lane) =
          make_float2(acc2[j][0], acc2[j][1]);
    }
    __syncwarp();
  }
}

// ---------------------------------------------------------------------------
// K2s: social attention + aggregation per (b,q). One warp per (b,q).
// grid 2560 x 256 thr (8 warps). Writes g_hoI.
// ---------------------------------------------------------------------------
#define SMEM_K2S ((4096 + 64 + 64 + 512) * 4)
__global__ __launch_bounds__(256) void k2s_attn(
    const int* __restrict__ u_user, const int* __restrict__ u_user_item,
    const float* __restrict__ agg_W, const float* __restrict__ agg_b,
    const float* __restrict__ atti_W2, const float* __restrict__ atti_b2) {
  extern __shared__ float sm[];
  float* sAgg = sm;           // 4096
  float* sbAgg = sm + 4096;   // 64
  float* sA2 = sm + 4160;     // 64
  float* sZ = sm + 4224;      // 8*64

  int tid = threadIdx.x, lane = tid & 31, w = tid >> 5;
  for (int i = tid; i < 4096; i += 256) sAgg[i] = agg_W[i];
  if (tid < 64) { sbAgg[tid] = agg_b[tid]; sA2[tid] = atti_W2[tid]; }
  __syncthreads();

  int gid = blockIdx.x * 8 + w;             // (b*40+q)
  float cb = atti_b2[0];
  int u = u_user[gid];
  float2 pc = *reinterpret_cast<const float2*>(g_uPA1 + (long)u * 64 + 2 * lane);
  float2 a2 = *reinterpret_cast<const float2*>(sA2 + 2 * lane);
  const int2* ip = reinterpret_cast<const int2*>(u_user_item + (long)gid * (P2 * 2));

  float den = 0.f, ax = 0.f, ay = 0.f;
#pragma unroll 4
  for (int r = 0; r < P2; r++) {
    int2 idx = ip[r];
    float m = (idx.x > 0) ? 1.f : 0.f;
    long off = ((long)idx.y * NI + idx.x) * 64 + 2 * lane;
    float2 t2 = *reinterpret_cast<const float2*>(g_T2 + off);
    float p = fmaxf(t2.x + m * pc.x, 0.f) * a2.x + fmaxf(t2.y + m * pc.y, 0.f) * a2.y;
#pragma unroll
    for (int o = 16; o; o >>= 1) p += __shfl_xor_sync(0xffffffffu, p, o);
    float al = expf(p + cb) * m;
    den += al;
    float2 t1 = *reinterpret_cast<const float2*>(g_T1 + off);
    ax = fmaf(al, t1.x, ax); ay = fmaf(al, t1.y, ay);
  }
  float dinv = 1.f / (den + EPSF);
  sZ[w * 64 + 2 * lane] = ax * dinv;
  sZ[w * 64 + 2 * lane + 1] = ay * dinv;
  __syncwarp();
  float ox = sbAgg[2 * lane], oy = sbAgg[2 * lane + 1];
#pragma unroll 8
  for (int k = 0; k < 64; k++) {
    float zk = sZ[w * 64 + k];
    float2 wk = *reinterpret_cast<const float2*>(sAgg + k * 64 + 2 * lane);
    ox = fmaf(zk, wk.x, ox); oy = fmaf(zk, wk.y, oy);
  }
  *reinterpret_cast<float2*>(g_hoI + (long)gid * 64 + 2 * lane) =
      make_float2(fmaxf(ox, 0.f), fmaxf(oy, 0.f));
}

// ---------------------------------------------------------------------------
// K1: item-branch attention + aggregation per b (100 rows, 8 warps strided).
// grid 512 x 256. Writes g_hiI.
// ---------------------------------------------------------------------------
#define SMEM_K1N ((4096 + 64 + 64 + 512 + 8 + 64) * 4)
__global__ __launch_bounds__(256) void k1_attn(
    const int* __restrict__ uids, const int* __restrict__ u_item,
    const float* __restrict__ agg_W, const float* __restrict__ agg_b,
    const float* __restrict__ atti_W2, const float* __restrict__ atti_b2) {
  extern __shared__ float sm[];
  float* sAgg = sm;            // 4096
  float* sbAgg = sm + 4096;    // 64
  float* sA2 = sm + 4160;      // 64
  float* sPx = sm + 4224;      // 8*64
  float* sPd = sm + 4736;      // 8
  float* sZ = sm + 4744;       // 64

  int tid = threadIdx.x, lane = tid & 31, w = tid >> 5;
  int b = blockIdx.x;
  for (int i = tid; i < 4096; i += 256) sAgg[i] = agg_W[i];
  if (tid < 64) { sbAgg[tid] = agg_b[tid]; sA2[tid] = atti_W2[tid]; }
  __syncthreads();

  float cb = atti_b2[0];
  int u = uids[b];
  float2 pc = *reinterpret_cast<const float2*>(g_uPA1 + (long)u * 64 + 2 * lane);
  float2 a2 = *reinterpret_cast<const float2*>(sA2 + 2 * lane);
  const int2* ip = reinterpret_cast<const int2*>(u_item + (long)b * (PP * 2));

  float den = 0.f, ax = 0.f, ay = 0.f;
  for (int r = w; r < PP; r += 8) {
    int2 idx = ip[r];
    float m = (idx.x > 0) ? 1.f : 0.f;
    long off = ((long)idx.y * NI + idx.x) * 64 + 2 * lane;
    float2 t2 = *reinterpret_cast<const float2*>(g_T2 + off);
    float p = fmaxf(t2.x + m * pc.x, 0.f) * a2.x + fmaxf(t2.y + m * pc.y, 0.f) * a2.y;
#pragma unroll
    for (int o = 16; o; o >>= 1) p += __shfl_xor_sync(0xffffffffu, p, o);
    float al = expf(p + cb) * m;
    den += al;
    float2 t1 = *reinterpret_cast<const float2*>(g_T1 + off);
    ax = fmaf(al, t1.x, ax); ay = fmaf(al, t1.y, ay);
  }
  sPx[w * 64 + 2 * lane] = ax;
  sPx[w * 64 + 2 * lane + 1] = ay;
  if (lane == 0) sPd[w] = den;
  __syncthreads();
  if (tid < 64) {
    float z = 0.f, d = 0.f;
#pragma unroll
    for (int ww = 0; ww < 8; ww++) { z += sPx[ww * 64 + tid]; d += sPd[ww]; }
    sZ[tid] = z * (1.f / (d + EPSF));
  }
  __syncthreads();
  if (tid < 64) {
    float s = sbAgg[tid];
#pragma unroll 8
    for (int k = 0; k < 64; k++) s = fmaf(sZ[k], sAgg[k * 64 + tid], s);
    g_hiI[b * 64 + tid] = fmaxf(s, 0.f);
  }
}

// ---------------------------------------------------------------------------
// K2b: beta attention over q + h_iS (unchanged; passed in round 1).
// ---------------------------------------------------------------------------
#define SMEM_K2B (20784 * 4)
__global__ __launch_bounds__(256) void k2b_user(
    const int* __restrict__ u_user, const float* __restrict__ user_table,
    const float* __restrict__ attu_W1, const float* __restrict__ attu_b1,
    const float* __restrict__ attu_W2, const float* __restrict__ attu_b2,
    const float* __restrict__ aggn_W, const float* __restrict__ aggn_b) {
  extern __shared__ float sm[];
  float* sU1 = sm;             float* sAggn = sm + 8192;
  float* sw2u = sm + 12288;    float* sb1u = sm + 12352;
  float* sbAggn = sm + 12416;  float* sZ = sm + 12480;
  float* sBeta = sm + 12544;   float* sRed = sm + 12584;
  float* sXT = sm + 12592;

  int b = blockIdx.x, tid = threadIdx.x, lane = tid & 31, w = tid >> 5;
  for (int i = tid; i < 8192; i += 256) sU1[i] = attu_W1[i];
  for (int i = tid; i < 4096; i += 256) sAggn[i] = aggn_W[i];
  if (tid < 64) { sw2u[tid] = attu_W2[tid]; sb1u[tid] = attu_b1[tid]; sbAggn[tid] = aggn_b[tid]; }
  __syncthreads();
  float cb2u = attu_b2[0];
  float* myXT = sXT + w * 1024;
  int rowbase = w * 5;
  float msk[5];
#pragma unroll
  for (int j = 0; j < 5; j++) {
    int row = rowbase + j;
    int uq = u_user[b * 40 + row];
    msk[j] = (uq > 0) ? 1.f : 0.f;
    const float* hp = g_hoI + (long)(b * 40 + row) * 64;
    const float* up = user_table + (long)uq * 64;
    myXT[lane * 8 + j] = hp[lane]; myXT[(lane + 32) * 8 + j] = hp[lane + 32];
    myXT[(lane + 64) * 8 + j] = up[lane]; myXT[(lane + 96) * 8 + j] = up[lane + 32];
  }
  __syncwarp();
  float acc[5][2];
#pragma unroll
  for (int j = 0; j < 5; j++) { acc[j][0] = sb1u[2 * lane]; acc[j][1] = sb1u[2 * lane + 1]; }
  wgemm<128>(myXT, sU1, lane, acc);
  float w0 = sw2u[2 * lane], w1 = sw2u[2 * lane + 1];
#pragma unroll
  for (int j = 0; j < 5; j++) {
    float p = fmaf(fmaxf(acc[j][0], 0.f), w0, fmaxf(acc[j][1], 0.f) * w1);
#pragma unroll
    for (int o = 16; o; o >>= 1) p += __shfl_xor_sync(0xffffffffu, p, o);
    if (lane == 0) sBeta[rowbase + j] = expf(p + cb2u) * msk[j];
  }
  __syncthreads();
  if (tid < 32) {
    float s = 0.f;
    for (int r = lane; r < 40; r += 32) s += sBeta[r];
#pragma unroll
    for (int o = 16; o; o >>= 1) s += __shfl_xor_sync(0xffffffffu, s, o);
    if (lane == 0) sRed[0] = s;
  }
  __syncthreads();
  float dinv = 1.f / (sRed[0] + EPSF);
  if (tid < 64) {
    float s = 0.f;
    for (int r = 0; r < 40; r++) s = fmaf(sBeta[r], g_hoI[(long)(b * 40 + r) * 64 + tid], s);
    sZ[tid] = s * dinv;
  }
  __syncthreads();
  if (tid < 64) {
    float s = sbAggn[tid];
    for (int k = 0; k < 64; k++) s = fmaf(sZ[k], sAggn[k * 64 + tid], s);
    g_hiS[b * 64 + tid] = fmaxf(s, 0.f);
  }
}

// ---------------------------------------------------------------------------
// K3: final 3-layer combine MLP (unchanged; passed in round 1).
// ---------------------------------------------------------------------------
#define SMEM_K3 (24768 * 4)
__global__ __launch_bounds__(256) void k3_final(
    const float* __restrict__ cm_W1, const float* __restrict__ cm_b1,
    const float* __restrict__ cm_W2, const float* __restrict__ cm_b2,
    const float* __restrict__ cm_W3, const float* __restrict__ cm_b3,
    float* __restrict__ out) {
  extern __shared__ float sm[];
  float* sC1 = sm;          float* sC2 = sm + 8192;   float* sC3 = sm + 12288;
  float* sb1 = sm + 16384;  float* sb2 = sm + 16448;  float* sb3 = sm + 16512;
  float* sXT = sm + 16576;

  int tid = threadIdx.x, lane = tid & 31, w = tid >> 5;
  for (int i = tid; i < 8192; i += 256) sC1[i] = cm_W1[i];
  for (int i = tid; i < 4096; i += 256) { sC2[i] = cm_W2[i]; sC3[i] = cm_W3[i]; }
  if (tid < 64) { sb1[tid] = cm_b1[tid]; sb2[tid] = cm_b2[tid]; sb3[tid] = cm_b3[tid]; }
  __syncthreads();
  float* myXT = sXT + w * 1024;
  int rowbase = blockIdx.x * 40 + w * 5;
#pragma unroll
  for (int j = 0; j < 5; j++) {
    int row = rowbase + j;
    float x0 = 0, x1 = 0, x2 = 0, x3 = 0;
    if (row < BB) {
      x0 = g_hiI[row * 64 + lane]; x1 = g_hiI[row * 64 + 32 + lane];
      x2 = g_hiS[row * 64 + lane]; x3 = g_hiS[row * 64 + 32 + lane];
    }
    myXT[lane * 8 + j] = x0; myXT[(lane + 32) * 8 + j] = x1;
    myXT[(lane + 64) * 8 + j] = x2; myXT[(lane + 96) * 8 + j] = x3;
  }
  __syncwarp();
  float acc[5][2];
#pragma unroll
  for (int j = 0; j < 5; j++) { acc[j][0] = sb1[2 * lane]; acc[j][1] = sb1[2 * lane + 1]; }
  wgemm<128>(myXT, sC1, lane, acc);
#pragma unroll
  for (int j = 0; j < 5; j++) { acc[j][0] = fmaxf(acc[j][0], 0.f); acc[j][1] = fmaxf(acc[j][1], 0.f); }
  __syncwarp(); wtrans(myXT, lane, acc); __syncwarp();
#pragma unroll
  for (int j = 0; j < 5; j++) { acc[j][0] = sb2[2 * lane]; acc[j][1] = sb2[2 * lane + 1]; }
  wgemm<64>(myXT, sC2, lane, acc);
#pragma unroll
  for (int j = 0; j < 5; j++) { acc[j][0] = fmaxf(acc[j][0], 0.f); acc[j][1] = fmaxf(acc[j][1], 0.f); }
  __syncwarp(); wtrans(myXT, lane, acc); __syncwarp();
#pragma unroll
  for (int j = 0; j < 5; j++) { acc[j][0] = sb3[2 * lane]; acc[j][1] = sb3[2 * lane + 1]; }
  wgemm<64>(myXT, sC3, lane, acc);
#pragma unroll
  for (int j = 0; j < 5; j++) {
    int row = rowbase + j;
    if (row < BB) {
      out[row * 64 + 2 * lane]     = fmaxf(acc[j][0], 0.f);
      out[row * 64 + 2 * lane + 1] = fmaxf(acc[j][1], 0.f);
    }
  }
}

// ---------------------------------------------------------------------------
extern "C" void kernel_launch(void* const* d_in, const int* in_sizes, int n_in,
                              void* d_out, int out_size) {
  const int* uids        = (const int*)d_in[0];
  const int* u_item      = (const int*)d_in[1];
  const int* u_user      = (const int*)d_in[2];
  const int* u_user_item = (const int*)d_in[3];
  const float* user_table = (const float*)d_in[4];
  const float* item_table = (const float*)d_in[5];
  const float* rate_table = (const float*)d_in[6];
  const float* gv_W1 = (const float*)d_in[7];   const float* gv_b1 = (const float*)d_in[8];
  const float* gv_W2 = (const float*)d_in[9];   const float* gv_b2 = (const float*)d_in[10];
  const float* atti_W1 = (const float*)d_in[11]; const float* atti_b1 = (const float*)d_in[12];
  const float* atti_W2 = (const float*)d_in[13]; const float* atti_b2 = (const float*)d_in[14];
  const float* agg_W = (const float*)d_in[15];   const float* agg_b = (const float*)d_in[16];
  const float* attu_W1 = (const float*)d_in[17]; const float* attu_b1 = (const float*)d_in[18];
  const float* attu_W2 = (const float*)d_in[19]; const float* attu_b2 = (const float*)d_in[20];
  const float* aggn_W = (const float*)d_in[21];  const float* aggn_b = (const float*)d_in[22];
  const float* cm_W1 = (const float*)d_in[23];   const float* cm_b1 = (const float*)d_in[24];
  const float* cm_W2 = (const float*)d_in[25];   const float* cm_b2 = (const float*)d_in[26];
  const float* cm_W3 = (const float*)d_in[27];   const float* cm_b3 = (const float*)d_in[28];
  float* out = (float*)d_out;

  cudaFuncSetAttribute(k0_proj,  cudaFuncAttributeMaxDynamicSharedMemorySize, SMEM_K0P);
  cudaFuncSetAttribute(k0_combo, cudaFuncAttributeMaxDynamicSharedMemorySize, SMEM_K0C);
  cudaFuncSetAttribute(k2s_attn, cudaFuncAttributeMaxDynamicSharedMemorySize, SMEM_K2S);
  cudaFuncSetAttribute(k1_attn,  cudaFuncAttributeMaxDynamicSharedMemorySize, SMEM_K1N);
  cudaFuncSetAttribute(k2b_user, cudaFuncAttributeMaxDynamicSharedMemorySize, SMEM_K2B);
  cudaFuncSetAttribute(k3_final, cudaFuncAttributeMaxDynamicSharedMemorySize, SMEM_K3);

  k0_rp<<<1, 384>>>(rate_table, gv_W1, gv_b1);
  k0_proj<<<625, 256, SMEM_K0P>>>(item_table, user_table, gv_W1, atti_W1);
  k0_combo<<<1875, 256, SMEM_K0C>>>(gv_W2, gv_b2, atti_W1, atti_b1);
  k2s_attn<<<2560, 256, SMEM_K2S>>>(u_user, u_user_item, agg_W, agg_b, atti_W2, atti_b2);
  k1_attn<<<512, 256, SMEM_K1N>>>(uids, u_item, agg_W, agg_b, atti_W2, atti_b2);
  k2b_user<<<512, 256, SMEM_K2B>>>(u_user, user_table, attu_W1, attu_b1, attu_W2,
                                   attu_b2, aggn_W, aggn_b);
  k3_final<<<13, 256, SMEM_K3>>>(cm_W1, cm_b1, cm_W2, cm_b2, cm_W3, cm_b3, out);
}

// round 4
// speedup vs baseline: 3.3154x; 1.4516x over previous
#include <cuda_runtime.h>

#define EPSF 1e-10f
#define NI 100000
#define NU 100000
#define NR 6
#define BB 512
#define PP 100
#define QQ 40
#define P2 40
#define XS 12  // XT row stride (floats): 48B, keeps LDS.128 alignment

typedef unsigned long long ull;

// ---------------- persistent scratch (static device memory) -----------------
__device__ float g_iP[NI * 64];            // item_table @ W1_top
__device__ float g_uPA1[NU * 64];          // user_table @ A1_bot
__device__ float g_rP[NR * 64];            // rate_table @ W1_bot + gv_b1
__device__ float g_Wf[64 * 64];            // W2 @ A1_top
__device__ float g_bf[64];                 // b2 @ A1_top + b1a
__device__ float g_T12[(long)NR * NI * 128]; // interleaved: [0:64)=T1(x_ia), [64:128)=T2
__device__ float g_hoI[BB * QQ * 64];
__device__ float g_hiI[BB * 64];
__device__ float g_hiS[BB * 64];

// ------------------------- f32x2 packed helpers ----------------------------
__device__ __forceinline__ ull pk2(float lo, float hi) {
  ull r; asm("mov.b64 %0, {%1,%2};" : "=l"(r) : "f"(lo), "f"(hi)); return r;
}
__device__ __forceinline__ void fma2(ull& d, ull a, ull b) {
  asm("fma.rn.f32x2 %0, %1, %2, %0;" : "+l"(d) : "l"(a), "l"(b));
}
__device__ __forceinline__ void upk(ull v, float& lo, float& hi) {
  asm("mov.b64 {%0,%1}, %2;" : "=f"(lo), "=f"(hi) : "l"(v));
}

// ---------------------------------------------------------------------------
// legacy warp GEMM (5 rows), used by small tail kernels k2b / k3
// ---------------------------------------------------------------------------
template <int K>
__device__ __forceinline__ void wgemm(const float* __restrict__ sXT,
                                      const float* __restrict__ sW,
                                      int lane, float acc[5][2]) {
#pragma unroll 8
  for (int k = 0; k < K; k++) {
    float2 w = *reinterpret_cast<const float2*>(sW + k * 64 + 2 * lane);
    float4 x4 = *reinterpret_cast<const float4*>(sXT + k * 8);
    float x5 = sXT[k * 8 + 4];
    acc[0][0] = fmaf(x4.x, w.x, acc[0][0]); acc[0][1] = fmaf(x4.x, w.y, acc[0][1]);
    acc[1][0] = fmaf(x4.y, w.x, acc[1][0]); acc[1][1] = fmaf(x4.y, w.y, acc[1][1]);
    acc[2][0] = fmaf(x4.z, w.x, acc[2][0]); acc[2][1] = fmaf(x4.z, w.y, acc[2][1]);
    acc[3][0] = fmaf(x4.w, w.x, acc[3][0]); acc[3][1] = fmaf(x4.w, w.y, acc[3][1]);
    acc[4][0] = fmaf(x5,  w.x, acc[4][0]);  acc[4][1] = fmaf(x5,  w.y, acc[4][1]);
  }
}
__device__ __forceinline__ void wtrans(float* sT, int lane, const float acc[5][2]) {
#pragma unroll
  for (int j = 0; j < 5; j++) {
    sT[(2 * lane) * 8 + j]     = acc[j][0];
    sT[(2 * lane + 1) * 8 + j] = acc[j][1];
  }
}

// ---------------------------------------------------------------------------
// K0_pre: rP = rate@W1_bot + b1 ; Wf = W2@A1_top ; bf = b2@A1_top + b1a
// 1 block x 1024 threads.
// ---------------------------------------------------------------------------
__global__ __launch_bounds__(1024) void k0_pre(
    const float* __restrict__ rate_table, const float* __restrict__ gv_W1,
    const float* __restrict__ gv_b1, const float* __restrict__ gv_W2,
    const float* __restrict__ gv_b2, const float* __restrict__ atti_W1,
    const float* __restrict__ atti_b1) {
  int t = threadIdx.x;
  if (t < NR * 64) {
    int r = t >> 6, c = t & 63;
    float s = gv_b1[c];
    const float* W1b = gv_W1 + 4096;
#pragma unroll 8
    for (int k = 0; k < 64; k++) s = fmaf(rate_table[r * 64 + k], W1b[k * 64 + c], s);
    g_rP[t] = s;
  }
  // Wf: 4096 entries, 4 per thread
#pragma unroll
  for (int e = 0; e < 4; e++) {
    int idx = t + e * 1024;
    int k = idx >> 6, c = idx & 63;
    float s = 0.f;
#pragma unroll 8
    for (int j = 0; j < 64; j++) s = fmaf(gv_W2[k * 64 + j], atti_W1[j * 64 + c], s);
    g_Wf[idx] = s;
  }
  if (t < 64) {
    float s = atti_b1[t];
#pragma unroll 8
    for (int j = 0; j < 64; j++) s = fmaf(gv_b2[j], atti_W1[j * 64 + t], s);
    g_bf[t] = s;
  }
}

// ---------------------------------------------------------------------------
// K0_proj (FFMA2): rows [0,NI): g_iP = item_table @ W1_top
//                  rows [NI,2NI): g_uPA1 = user_table @ A1_bot
// grid 500 x 256; 5 iters x 8 warps x 10 rows = 400 rows/CTA.
// ---------------------------------------------------------------------------
#define SMEM_K0P ((4096 + 4096 + 8 * 64 * XS) * 4)
__global__ __launch_bounds__(256) void k0_proj(
    const float* __restrict__ item_table, const float* __restrict__ user_table,
    const float* __restrict__ gv_W1, const float* __restrict__ atti_W1) {
  extern __shared__ float sm[];
  float* sWa = sm;            // W1_top
  float* sWb = sm + 4096;     // A1_bot
  float* sXT = sm + 8192;

  int tid = threadIdx.x, lane = tid & 31, w = tid >> 5;
  for (int i = tid; i < 4096; i += 256) { sWa[i] = gv_W1[i]; sWb[i] = atti_W1[4096 + i]; }
  __syncthreads();
  float* myXT = sXT + w * (64 * XS);

  for (int it = 0; it < 5; it++) {
    int rid0 = blockIdx.x * 400 + it * 80 + w * 10;
    bool half2 = (rid0 >= NI);
    const float* src = half2 ? user_table : item_table;
    const float* sW = half2 ? sWb : sWa;
    float* dst = half2 ? g_uPA1 : g_iP;
    int base = half2 ? (rid0 - NI) : rid0;
#pragma unroll
    for (int j = 0; j < 10; j++) {
      const float* sp = src + (long)(base + j) * 64;
      myXT[lane * XS + j] = sp[lane];
      myXT[(lane + 32) * XS + j] = sp[lane + 32];
    }
    __syncwarp();
    ull a0[5], a1[5];
#pragma unroll
    for (int p = 0; p < 5; p++) { a0[p] = 0ull; a1[p] = 0ull; }
#pragma unroll 8
    for (int k = 0; k < 64; k++) {
      float4 xa = *reinterpret_cast<const float4*>(myXT + k * XS);
      float4 xb = *reinterpret_cast<const float4*>(myXT + k * XS + 4);
      float2 xc = *reinterpret_cast<const float2*>(myXT + k * XS + 8);
      ull xp0 = pk2(xa.x, xa.y), xp1 = pk2(xa.z, xa.w);
      ull xp2 = pk2(xb.x, xb.y), xp3 = pk2(xb.z, xb.w);
      ull xp4 = pk2(xc.x, xc.y);
      float2 wv = *reinterpret_cast<const float2*>(sW + k * 64 + 2 * lane);
      ull w0 = pk2(wv.x, wv.x), w1 = pk2(wv.y, wv.y);
      fma2(a0[0], xp0, w0); fma2(a1[0], xp0, w1);
      fma2(a0[1], xp1, w0); fma2(a1[1], xp1, w1);
      fma2(a0[2], xp2, w0); fma2(a1[2], xp2, w1);
      fma2(a0[3], xp3, w0); fma2(a1[3], xp3, w1);
      fma2(a0[4], xp4, w0); fma2(a1[4], xp4, w1);
    }
#pragma unroll
    for (int p = 0; p < 5; p++) {
      float r0c0, r1c0, r0c1, r1c1;
      upk(a0[p], r0c0, r1c0); upk(a1[p], r0c1, r1c1);
      *reinterpret_cast<float2*>(dst + (long)(base + 2 * p) * 64 + 2 * lane) =
          make_float2(r0c0, r0c1);
      *reinterpret_cast<float2*>(dst + (long)(base + 2 * p + 1) * 64 + 2 * lane) =
          make_float2(r1c0, r1c1);
    }
    __syncwarp();
  }
}

// ---------------------------------------------------------------------------
// K0_combo (FFMA2, fused dual GEMM): for all 600000 (rate,item) combos:
//   h1 = relu(iP[i] + rP[r])
//   T1 = h1 @ W2 + b2 ; T2 = h1 @ Wf + bf
// interleaved out: g_T12[rid*128 + {0:64 T1, 64:128 T2}]
// grid 1875 x 256; 4 iters x 8 warps x 10 rows = 320 rows/CTA.
// ---------------------------------------------------------------------------
#define SMEM_K0C ((4096 + 4096 + 8 * 64 * XS + 384 + 64 + 64) * 4)
__global__ __launch_bounds__(256) void k0_combo(
    const float* __restrict__ gv_W2, const float* __restrict__ gv_b2) {
  extern __shared__ float sm[];
  float* sW2 = sm;                  // 4096
  float* sWf = sm + 4096;           // 4096
  float* sXT = sm + 8192;           // 8*64*XS = 6144
  float* srP = sm + 8192 + 6144;    // 384
  float* sb2 = srP + 384;           // 64
  float* sbf = sb2 + 64;            // 64

  int tid = threadIdx.x, lane = tid & 31, w = tid >> 5;
  for (int i = tid; i < 4096; i += 256) { sW2[i] = gv_W2[i]; sWf[i] = g_Wf[i]; }
  for (int i = tid; i < 384; i += 256) srP[i] = g_rP[i];
  if (tid < 64) { sb2[tid] = gv_b2[tid]; sbf[tid] = g_bf[tid]; }
  __syncthreads();
  float* myXT = sXT + w * (64 * XS);

  float2 bb1 = *reinterpret_cast<const float2*>(sb2 + 2 * lane);
  float2 bb2 = *reinterpret_cast<const float2*>(sbf + 2 * lane);
  ull b10 = pk2(bb1.x, bb1.x), b11 = pk2(bb1.y, bb1.y);
  ull b20 = pk2(bb2.x, bb2.x), b21 = pk2(bb2.y, bb2.y);

  for (int it = 0; it < 4; it++) {
    int rid0 = blockIdx.x * 320 + it * 80 + w * 10;
    int r = rid0 / NI;
    int i0 = rid0 - r * NI;
    const float* rp = srP + r * 64;
    float rp0 = rp[lane], rp1 = rp[lane + 32];
#pragma unroll
    for (int j = 0; j < 10; j++) {
      const float* ip = g_iP + (long)(i0 + j) * 64;
      myXT[lane * XS + j] = fmaxf(ip[lane] + rp0, 0.f);
      myXT[(lane + 32) * XS + j] = fmaxf(ip[lane + 32] + rp1, 0.f);
    }
    __syncwarp();
    ull a10[5], a11[5], a20[5], a21[5];
#pragma unroll
    for (int p = 0; p < 5; p++) { a10[p] = b10; a11[p] = b11; a20[p] = b20; a21[p] = b21; }
#pragma unroll 8
    for (int k = 0; k < 64; k++) {
      float4 xa = *reinterpret_cast<const float4*>(myXT + k * XS);
      float4 xb = *reinterpret_cast<const float4*>(myXT + k * XS + 4);
      float2 xc = *reinterpret_cast<const float2*>(myXT + k * XS + 8);
      ull xp0 = pk2(xa.x, xa.y), xp1 = pk2(xa.z, xa.w);
      ull xp2 = pk2(xb.x, xb.y), xp3 = pk2(xb.z, xb.w);
      ull xp4 = pk2(xc.x, xc.y);
      float2 w1v = *reinterpret_cast<const float2*>(sW2 + k * 64 + 2 * lane);
      float2 w2v = *reinterpret_cast<const float2*>(sWf + k * 64 + 2 * lane);
      ull w10 = pk2(w1v.x, w1v.x), w11 = pk2(w1v.y, w1v.y);
      ull w20 = pk2(w2v.x, w2v.x), w21 = pk2(w2v.y, w2v.y);
      fma2(a10[0], xp0, w10); fma2(a11[0], xp0, w11);
      fma2(a10[1], xp1, w10); fma2(a11[1], xp1, w11);
      fma2(a10[2], xp2, w10); fma2(a11[2], xp2, w11);
      fma2(a10[3], xp3, w10); fma2(a11[3], xp3, w11);
      fma2(a10[4], xp4, w10); fma2(a11[4], xp4, w11);
      fma2(a20[0], xp0, w20); fma2(a21[0], xp0, w21);
      fma2(a20[1], xp1, w20); fma2(a21[1], xp1, w21);
      fma2(a20[2], xp2, w20); fma2(a21[2], xp2, w21);
      fma2(a20[3], xp3, w20); fma2(a21[3], xp3, w21);
      fma2(a20[4], xp4, w20); fma2(a21[4], xp4, w21);
    }
#pragma unroll
    for (int p = 0; p < 5; p++) {
      float r0c0, r1c0, r0c1, r1c1;
      long o0 = (long)(rid0 + 2 * p) * 128 + 2 * lane;
      long o1 = (long)(rid0 + 2 * p + 1) * 128 + 2 * lane;
      upk(a10[p], r0c0, r1c0); upk(a11[p], r0c1, r1c1);
      *reinterpret_cast<float2*>(g_T12 + o0) = make_float2(r0c0, r0c1);
      *reinterpret_cast<float2*>(g_T12 + o1) = make_float2(r1c0, r1c1);
      upk(a20[p], r0c0, r1c0); upk(a21[p], r0c1, r1c1);
      *reinterpret_cast<float2*>(g_T12 + o0 + 64) = make_float2(r0c0, r0c1);
      *reinterpret_cast<float2*>(g_T12 + o1 + 64) = make_float2(r1c0, r1c1);
    }
    __syncwarp();
  }
}

// ---------------------------------------------------------------------------
// K2s: social attention + aggregation per (b,q). One warp per (b,q).
// ---------------------------------------------------------------------------
#define SMEM_K2S ((4096 + 64 + 64 + 512) * 4)
__global__ __launch_bounds__(256) void k2s_attn(
    const int* __restrict__ u_user, const int* __restrict__ u_user_item,
    const float* __restrict__ agg_W, const float* __restrict__ agg_b,
    const float* __restrict__ atti_W2, const float* __restrict__ atti_b2) {
  extern __shared__ float sm[];
  float* sAgg = sm;           // 4096
  float* sbAgg = sm + 4096;   // 64
  float* sA2 = sm + 4160;     // 64
  float* sZ = sm + 4224;      // 8*64

  int tid = threadIdx.x, lane = tid & 31, w = tid >> 5;
  for (int i = tid; i < 4096; i += 256) sAgg[i] = agg_W[i];
  if (tid < 64) { sbAgg[tid] = agg_b[tid]; sA2[tid] = atti_W2[tid]; }
  __syncthreads();

  int gid = blockIdx.x * 8 + w;             // (b*40+q)
  float cb = atti_b2[0];
  int u = u_user[gid];
  float2 pc = *reinterpret_cast<const float2*>(g_uPA1 + (long)u * 64 + 2 * lane);
  float2 a2 = *reinterpret_cast<const float2*>(sA2 + 2 * lane);
  const int2* ip = reinterpret_cast<const int2*>(u_user_item + (long)gid * (P2 * 2));

  float den = 0.f, ax = 0.f, ay = 0.f;
#pragma unroll 4
  for (int r = 0; r < P2; r++) {
    int2 idx = ip[r];
    float m = (idx.x > 0) ? 1.f : 0.f;
    long off = ((long)idx.y * NI + idx.x) * 128 + 2 * lane;
    float2 t2 = *reinterpret_cast<const float2*>(g_T12 + off + 64);
    float2 t1 = *reinterpret_cast<const float2*>(g_T12 + off);
    float p = fmaxf(t2.x + m * pc.x, 0.f) * a2.x + fmaxf(t2.y + m * pc.y, 0.f) * a2.y;
#pragma unroll
    for (int o = 16; o; o >>= 1) p += __shfl_xor_sync(0xffffffffu, p, o);
    float al = __expf(p + cb) * m;
    den += al;
    ax = fmaf(al, t1.x, ax); ay = fmaf(al, t1.y, ay);
  }
  float dinv = 1.f / (den + EPSF);
  sZ[w * 64 + 2 * lane] = ax * dinv;
  sZ[w * 64 + 2 * lane + 1] = ay * dinv;
  __syncwarp();
  float ox = sbAgg[2 * lane], oy = sbAgg[2 * lane + 1];
#pragma unroll 8
  for (int k = 0; k < 64; k++) {
    float zk = sZ[w * 64 + k];
    float2 wk = *reinterpret_cast<const float2*>(sAgg + k * 64 + 2 * lane);
    ox = fmaf(zk, wk.x, ox); oy = fmaf(zk, wk.y, oy);
  }
  *reinterpret_cast<float2*>(g_hoI + (long)gid * 64 + 2 * lane) =
      make_float2(fmaxf(ox, 0.f), fmaxf(oy, 0.f));
}

// ---------------------------------------------------------------------------
// K1: item-branch attention + aggregation per b (100 rows, 8 warps strided).
// ---------------------------------------------------------------------------
#define SMEM_K1N ((4096 + 64 + 64 + 512 + 8 + 64) * 4)
__global__ __launch_bounds__(256) void k1_attn(
    const int* __restrict__ uids, const int* __restrict__ u_item,
    const float* __restrict__ agg_W, const float* __restrict__ agg_b,
    const float* __restrict__ atti_W2, const float* __restrict__ atti_b2) {
  extern __shared__ float sm[];
  float* sAgg = sm;            // 4096
  float* sbAgg = sm + 4096;    // 64
  float* sA2 = sm + 4160;      // 64
  float* sPx = sm + 4224;      // 8*64
  float* sPd = sm + 4736;      // 8
  float* sZ = sm + 4744;       // 64

  int tid = threadIdx.x, lane = tid & 31, w = tid >> 5;
  int b = blockIdx.x;
  for (int i = tid; i < 4096; i += 256) sAgg[i] = agg_W[i];
  if (tid < 64) { sbAgg[tid] = agg_b[tid]; sA2[tid] = atti_W2[tid]; }
  __syncthreads();

  float cb = atti_b2[0];
  int u = uids[b];
  float2 pc = *reinterpret_cast<const float2*>(g_uPA1 + (long)u * 64 + 2 * lane);
  float2 a2 = *reinterpret_cast<const float2*>(sA2 + 2 * lane);
  const int2* ip = reinterpret_cast<const int2*>(u_item + (long)b * (PP * 2));

  float den = 0.f, ax = 0.f, ay = 0.f;
  for (int r = w; r < PP; r += 8) {
    int2 idx = ip[r];
    float m = (idx.x > 0) ? 1.f : 0.f;
    long off = ((long)idx.y * NI + idx.x) * 128 + 2 * lane;
    float2 t2 = *reinterpret_cast<const float2*>(g_T12 + off + 64);
    float2 t1 = *reinterpret_cast<const float2*>(g_T12 + off);
    float p = fmaxf(t2.x + m * pc.x, 0.f) * a2.x + fmaxf(t2.y + m * pc.y, 0.f) * a2.y;
#pragma unroll
    for (int o = 16; o; o >>= 1) p += __shfl_xor_sync(0xffffffffu, p, o);
    float al = __expf(p + cb) * m;
    den += al;
    ax = fmaf(al, t1.x, ax); ay = fmaf(al, t1.y, ay);
  }
  sPx[w * 64 + 2 * lane] = ax;
  sPx[w * 64 + 2 * lane + 1] = ay;
  if (lane == 0) sPd[w] = den;
  __syncthreads();
  if (tid < 64) {
    float z = 0.f, d = 0.f;
#pragma unroll
    for (int ww = 0; ww < 8; ww++) { z += sPx[ww * 64 + tid]; d += sPd[ww]; }
    sZ[tid] = z * (1.f / (d + EPSF));
  }
  __syncthreads();
  if (tid < 64) {
    float s = sbAgg[tid];
#pragma unroll 8
    for (int k = 0; k < 64; k++) s = fmaf(sZ[k], sAgg[k * 64 + tid], s);
    g_hiI[b * 64 + tid] = fmaxf(s, 0.f);
  }
}

// ---------------------------------------------------------------------------
// K2b: beta attention over q + h_iS (unchanged).
// ---------------------------------------------------------------------------
#define SMEM_K2B (20784 * 4)
__global__ __launch_bounds__(256) void k2b_user(
    const int* __restrict__ u_user, const float* __restrict__ user_table,
    const float* __restrict__ attu_W1, const float* __restrict__ attu_b1,
    const float* __restrict__ attu_W2, const float* __restrict__ attu_b2,
    const float* __restrict__ aggn_W, const float* __restrict__ aggn_b) {
  extern __shared__ float sm[];
  float* sU1 = sm;             float* sAggn = sm + 8192;
  float* sw2u = sm + 12288;    float* sb1u = sm + 12352;
  float* sbAggn = sm + 12416;  float* sZ = sm + 12480;
  float* sBeta = sm + 12544;   float* sRed = sm + 12584;
  float* sXT = sm + 12592;

  int b = blockIdx.x, tid = threadIdx.x, lane = tid & 31, w = tid >> 5;
  for (int i = tid; i < 8192; i += 256) sU1[i] = attu_W1[i];
  for (int i = tid; i < 4096; i += 256) sAggn[i] = aggn_W[i];
  if (tid < 64) { sw2u[tid] = attu_W2[tid]; sb1u[tid] = attu_b1[tid]; sbAggn[tid] = aggn_b[tid]; }
  __syncthreads();
  float cb2u = attu_b2[0];
  float* myXT = sXT + w * 1024;
  int rowbase = w * 5;
  float msk[5];
#pragma unroll
  for (int j = 0; j < 5; j++) {
    int row = rowbase + j;
    int uq = u_user[b * 40 + row];
    msk[j] = (uq > 0) ? 1.f : 0.f;
    const float* hp = g_hoI + (long)(b * 40 + row) * 64;
    const float* up = user_table + (long)uq * 64;
    myXT[lane * 8 + j] = hp[lane]; myXT[(lane + 32) * 8 + j] = hp[lane + 32];
    myXT[(lane + 64) * 8 + j] = up[lane]; myXT[(lane + 96) * 8 + j] = up[lane + 32];
  }
  __syncwarp();
  float acc[5][2];
#pragma unroll
  for (int j = 0; j < 5; j++) { acc[j][0] = sb1u[2 * lane]; acc[j][1] = sb1u[2 * lane + 1]; }
  wgemm<128>(myXT, sU1, lane, acc);
  float w0 = sw2u[2 * lane], w1 = sw2u[2 * lane + 1];
#pragma unroll
  for (int j = 0; j < 5; j++) {
    float p = fmaf(fmaxf(acc[j][0], 0.f), w0, fmaxf(acc[j][1], 0.f) * w1);
#pragma unroll
    for (int o = 16; o; o >>= 1) p += __shfl_xor_sync(0xffffffffu, p, o);
    if (lane == 0) sBeta[rowbase + j] = expf(p + cb2u) * msk[j];
  }
  __syncthreads();
  if (tid < 32) {
    float s = 0.f;
    for (int r = lane; r < 40; r += 32) s += sBeta[r];
#pragma unroll
    for (int o = 16; o; o >>= 1) s += __shfl_xor_sync(0xffffffffu, s, o);
    if (lane == 0) sRed[0] = s;
  }
  __syncthreads();
  float dinv = 1.f / (sRed[0] + EPSF);
  if (tid < 64) {
    float s = 0.f;
    for (int r = 0; r < 40; r++) s = fmaf(sBeta[r], g_hoI[(long)(b * 40 + r) * 64 + tid], s);
    sZ[tid] = s * dinv;
  }
  __syncthreads();
  if (tid < 64) {
    float s = sbAggn[tid];
    for (int k = 0; k < 64; k++) s = fmaf(sZ[k], sAggn[k * 64 + tid], s);
    g_hiS[b * 64 + tid] = fmaxf(s, 0.f);
  }
}

// ---------------------------------------------------------------------------
// K3: final 3-layer combine MLP (unchanged).
// ---------------------------------------------------------------------------
#define SMEM_K3 (24768 * 4)
__global__ __launch_bounds__(256) void k3_final(
    const float* __restrict__ cm_W1, const float* __restrict__ cm_b1,
    const float* __restrict__ cm_W2, const float* __restrict__ cm_b2,
    const float* __restrict__ cm_W3, const float* __restrict__ cm_b3,
    float* __restrict__ out) {
  extern __shared__ float sm[];
  float* sC1 = sm;          float* sC2 = sm + 8192;   float* sC3 = sm + 12288;
  float* sb1 = sm + 16384;  float* sb2 = sm + 16448;  float* sb3 = sm + 16512;
  float* sXT = sm + 16576;

  int tid = threadIdx.x, lane = tid & 31, w = tid >> 5;
  for (int i = tid; i < 8192; i += 256) sC1[i] = cm_W1[i];
  for (int i = tid; i < 4096; i += 256) { sC2[i] = cm_W2[i]; sC3[i] = cm_W3[i]; }
  if (tid < 64) { sb1[tid] = cm_b1[tid]; sb2[tid] = cm_b2[tid]; sb3[tid] = cm_b3[tid]; }
  __syncthreads();
  float* myXT = sXT + w * 1024;
  int rowbase = blockIdx.x * 40 + w * 5;
#pragma unroll
  for (int j = 0; j < 5; j++) {
    int row = rowbase + j;
    float x0 = 0, x1 = 0, x2 = 0, x3 = 0;
    if (row < BB) {
      x0 = g_hiI[row * 64 + lane]; x1 = g_hiI[row * 64 + 32 + lane];
      x2 = g_hiS[row * 64 + lane]; x3 = g_hiS[row * 64 + 32 + lane];
    }
    myXT[lane * 8 + j] = x0; myXT[(lane + 32) * 8 + j] = x1;
    myXT[(lane + 64) * 8 + j] = x2; myXT[(lane + 96) * 8 + j] = x3;
  }
  __syncwarp();
  float acc[5][2];
#pragma unroll
  for (int j = 0; j < 5; j++) { acc[j][0] = sb1[2 * lane]; acc[j][1] = sb1[2 * lane + 1]; }
  wgemm<128>(myXT, sC1, lane, acc);
#pragma unroll
  for (int j = 0; j < 5; j++) { acc[j][0] = fmaxf(acc[j][0], 0.f); acc[j][1] = fmaxf(acc[j][1], 0.f); }
  __syncwarp(); wtrans(myXT, lane, acc); __syncwarp();
#pragma unroll
  for (int j = 0; j < 5; j++) { acc[j][0] = sb2[2 * lane]; acc[j][1] = sb2[2 * lane + 1]; }
  wgemm<64>(myXT, sC2, lane, acc);
#pragma unroll
  for (int j = 0; j < 5; j++) { acc[j][0] = fmaxf(acc[j][0], 0.f); acc[j][1] = fmaxf(acc[j][1], 0.f); }
  __syncwarp(); wtrans(myXT, lane, acc); __syncwarp();
#pragma unroll
  for (int j = 0; j < 5; j++) { acc[j][0] = sb3[2 * lane]; acc[j][1] = sb3[2 * lane + 1]; }
  wgemm<64>(myXT, sC3, lane, acc);
#pragma unroll
  for (int j = 0; j < 5; j++) {
    int row = rowbase + j;
    if (row < BB) {
      out[row * 64 + 2 * lane]     = fmaxf(acc[j][0], 0.f);
      out[row * 64 + 2 * lane + 1] = fmaxf(acc[j][1], 0.f);
    }
  }
}

// ---------------------------------------------------------------------------
extern "C" void kernel_launch(void* const* d_in, const int* in_sizes, int n_in,
                              void* d_out, int out_size) {
  const int* uids        = (const int*)d_in[0];
  const int* u_item      = (const int*)d_in[1];
  const int* u_user      = (const int*)d_in[2];
  const int* u_user_item = (const int*)d_in[3];
  const float* user_table = (const float*)d_in[4];
  const float* item_table = (const float*)d_in[5];
  const float* rate_table = (const float*)d_in[6];
  const float* gv_W1 = (const float*)d_in[7];   const float* gv_b1 = (const float*)d_in[8];
  const float* gv_W2 = (const float*)d_in[9];   const float* gv_b2 = (const float*)d_in[10];
  const float* atti_W1 = (const float*)d_in[11]; const float* atti_b1 = (const float*)d_in[12];
  const float* atti_W2 = (const float*)d_in[13]; const float* atti_b2 = (const float*)d_in[14];
  const float* agg_W = (const float*)d_in[15];   const float* agg_b = (const float*)d_in[16];
  const float* attu_W1 = (const float*)d_in[17]; const float* attu_b1 = (const float*)d_in[18];
  const float* attu_W2 = (const float*)d_in[19]; const float* attu_b2 = (const float*)d_in[20];
  const float* aggn_W = (const float*)d_in[21];  const float* aggn_b = (const float*)d_in[22];
  const float* cm_W1 = (const float*)d_in[23];   const float* cm_b1 = (const float*)d_in[24];
  const float* cm_W2 = (const float*)d_in[25];   const float* cm_b2 = (const float*)d_in[26];
  const float* cm_W3 = (const float*)d_in[27];   const float* cm_b3 = (const float*)d_in[28];
  float* out = (float*)d_out;

  cudaFuncSetAttribute(k0_proj,  cudaFuncAttributeMaxDynamicSharedMemorySize, SMEM_K0P);
  cudaFuncSetAttribute(k0_combo, cudaFuncAttributeMaxDynamicSharedMemorySize, SMEM_K0C);
  cudaFuncSetAttribute(k2s_attn, cudaFuncAttributeMaxDynamicSharedMemorySize, SMEM_K2S);
  cudaFuncSetAttribute(k1_attn,  cudaFuncAttributeMaxDynamicSharedMemorySize, SMEM_K1N);
  cudaFuncSetAttribute(k2b_user, cudaFuncAttributeMaxDynamicSharedMemorySize, SMEM_K2B);
  cudaFuncSetAttribute(k3_final, cudaFuncAttributeMaxDynamicSharedMemorySize, SMEM_K3);

  k0_pre<<<1, 1024>>>(rate_table, gv_W1, gv_b1, gv_W2, gv_b2, atti_W1, atti_b1);
  k0_proj<<<500, 256, SMEM_K0P>>>(item_table, user_table, gv_W1, atti_W1);
  k0_combo<<<1875, 256, SMEM_K0C>>>(gv_W2, gv_b2);
  k2s_attn<<<2560, 256, SMEM_K2S>>>(u_user, u_user_item, agg_W, agg_b, atti_W2, atti_b2);
  k1_attn<<<512, 256, SMEM_K1N>>>(uids, u_item, agg_W, agg_b, atti_W2, atti_b2);
  k2b_user<<<512, 256, SMEM_K2B>>>(u_user, user_table, attu_W1, attu_b1, attu_W2,
                                   attu_b2, aggn_W, aggn_b);
  k3_final<<<13, 256, SMEM_K3>>>(cm_W1, cm_b1, cm_W2, cm_b2, cm_W3, cm_b3, out);
}